// round 6
// baseline (speedup 1.0000x reference)
#include <cuda_runtime.h>
#include <cstdint>

#define MAXDISP 48
#define NG      40
#define CPG     8
#define CCH     12
#define CIN1    64
#define CO      32
#define BB      4
#define HH_     64
#define WW_     128
#define DD_     48
#define HW      (HH_*WW_)         /* 8192 */
#define DHW     ((size_t)DD_*HW)  /* 393216 */

// Scratch (device globals — no allocation APIs used)
__device__ float g_vol[(size_t)BB*CIN1*DD_*HH_*WW_];
__device__ float g_x1 [(size_t)BB*CO  *DD_*HH_*WW_];

// Packed fp32x2 FMA (Blackwell): d = a*b + d per 32-bit half, exact fp32.
#define FFMA2(acc, a, b) \
    asm volatile("fma.rn.f32x2 %0, %1, %2, %0;" : "+l"(acc) : "l"(a), "l"(b))
#define UNPACK2(lo, hi, src) \
    asm volatile("mov.b64 {%0, %1}, %2;" : "=f"(lo), "=f"(hi) : "l"(src))

// ---------------------------------------------------------------------------
// Kernel 1: build cost volume.  blockIdx.x = b*64+h, blockIdx.y = chunk (0..10)
// ---------------------------------------------------------------------------
__global__ __launch_bounds__(256)
void build_volume_kernel(const float* __restrict__ lg,
                         const float* __restrict__ rg,
                         const float* __restrict__ lc,
                         const float* __restrict__ rc)
{
    __shared__ float lgs[32][WW_];
    __shared__ float rgs[32][WW_];

    const int b     = blockIdx.x / HH_;
    const int h     = blockIdx.x % HH_;
    const int chunk = blockIdx.y;
    const int tid   = threadIdx.x;
    const int w     = tid & 127;
    const int t2    = tid >> 7;   // 0..1

    if (chunk < 10) {
        for (int i = tid; i < 32 * WW_; i += 256) {
            int ch = i >> 7;
            int ww = i & 127;
            int cg = chunk * 32 + ch;
            lgs[ch][ww] = lg[((size_t)(b * 320 + cg) * HH_ + h) * WW_ + ww];
            rgs[ch][ww] = rg[((size_t)(b * 320 + cg) * HH_ + h) * WW_ + ww];
        }
        __syncthreads();

        for (int gi = 0; gi < 2; ++gi) {
            int g = t2 + gi * 2;
            float lreg[CPG];
            #pragma unroll
            for (int c = 0; c < CPG; ++c) lreg[c] = lgs[g * CPG + c][w];

            int gout = chunk * 4 + g;
            float* outp = g_vol + (size_t)(b * CIN1 + gout) * DHW + (size_t)h * WW_ + w;
            #pragma unroll 4
            for (int d = 0; d < DD_; ++d) {
                float v = 0.f;
                if (w >= d) {
                    float s = 0.f;
                    #pragma unroll
                    for (int c = 0; c < CPG; ++c)
                        s += lreg[c] * rgs[g * CPG + c][w - d];
                    v = s * (1.0f / CPG);
                }
                outp[(size_t)d * HW] = v;
            }
        }
    } else {
        for (int i = tid; i < 24 * WW_; i += 256) {
            int ch = i >> 7;
            int ww = i & 127;
            lgs[ch][ww] = (ch < 12)
                ? lc[((size_t)(b * CCH + ch)      * HH_ + h) * WW_ + ww]
                : rc[((size_t)(b * CCH + (ch-12)) * HH_ + h) * WW_ + ww];
        }
        __syncthreads();

        for (int idx = t2; idx < 24 * DD_; idx += 2) {
            int ch = idx / DD_;
            int d  = idx % DD_;
            float v = 0.f;
            if (w >= d) v = (ch < 12) ? lgs[ch][w] : lgs[ch][w - d];
            g_vol[(size_t)(b * CIN1 + 40 + ch) * DHW + (size_t)d * HW + (size_t)h * WW_ + w] = v;
        }
    }
}

// ---------------------------------------------------------------------------
// Kernel 2/3: 3x3x3 conv + BN + ReLU via packed fma.rn.f32x2.
//   Input pairs pre-duplicated (v,v) in smem -> broadcast operand is one
//   aligned LDS.64, no pack MOVs in the mainloop.
//   Thread: 2 (d,h)-pos x 4 co-pairs x 4 w = 32 x f32x2 accumulators.
// ---------------------------------------------------------------------------
#define SW_ROW 36
#define SIN_H  216           /* 6*36 */
#define SIN_C  1296          /* 6*6*36 */
#define CC     4
#define SIN2_BYTES (CC * SIN_C * 8)          /* 41472 */
#define SW_BYTES   (CC * 27 * 32 * 4)        /* 13824 */
#define SMEM_TOTAL_CONV (SIN2_BYTES + SW_BYTES)

template<int CIN>
__global__ __launch_bounds__(256, 2)
void conv3d_bn_relu(const float* __restrict__ in,
                    const float* __restrict__ wgt,     // [CO][CIN][3][3][3]
                    const float* __restrict__ gamma,
                    const float* __restrict__ beta,
                    const float* __restrict__ mean,
                    const float* __restrict__ var,
                    float* __restrict__ out,
                    int z0)
{
    extern __shared__ __align__(16) char smem_raw[];
    float2* s_in2 = reinterpret_cast<float2*>(smem_raw);           // [CC][6][6][36] dup pairs
    float*  s_w   = reinterpret_cast<float*>(smem_raw + SIN2_BYTES); // [CC][27][32]

    const int wt = blockIdx.x;            // 0..3
    const int ht = blockIdx.y;            // 0..15
    const int bz = blockIdx.z + z0;
    const int b  = bz / 12;
    const int dt = bz % 12;
    const int d0 = dt * 4, h0 = ht * 4, w0 = wt * 32;

    const int tid = threadIdx.x;
    const int cob = (tid >> 6) * 8;       // 0,8,16,24
    const int sp  = tid & 63;
    const int wb  = (sp & 7) * 4;         // 0..28
    const int dh2 = sp >> 3;              // 0..7

    uint64_t acc2[2][4][4];               // [i][co-pair][w]
    #pragma unroll
    for (int i = 0; i < 2; ++i)
        #pragma unroll
        for (int op = 0; op < 4; ++op)
            #pragma unroll
            for (int j = 0; j < 4; ++j) acc2[i][op][j] = 0ull;

    for (int ci0 = 0; ci0 < CIN; ci0 += CC) {
        // input tile (halo, zero-padded), stored as duplicated (v,v) pairs
        for (int i = tid; i < CC * SIN_C; i += 256) {
            int c  = i / SIN_C;
            int r  = i % SIN_C;
            int dd = r / SIN_H;
            int r2 = r % SIN_H;
            int hh = r2 / SW_ROW;
            int ww = r2 % SW_ROW;
            int id = d0 + dd - 1;
            int ih = h0 + hh - 1;
            int iw = w0 + ww - 1;
            float v = 0.f;
            if (id >= 0 && id < DD_ && ih >= 0 && ih < HH_ && iw >= 0 && iw < WW_ && ww < 34)
                v = in[(((size_t)(b * CIN + ci0 + c) * DD_ + id) * HH_ + ih) * WW_ + iw];
            s_in2[i] = make_float2(v, v);
        }
        // weights: s_w[(c*27+k)*32+co] = wgt[(co*CIN + ci0+c)*27 + k]
        for (int i = tid; i < CC * 27 * 32; i += 256) {
            int co = i & 31;
            int ck = i >> 5;
            int c  = ck / 27;
            int k  = ck % 27;
            s_w[i] = wgt[((size_t)co * CIN + ci0 + c) * 27 + k];
        }
        __syncthreads();

        #pragma unroll 1
        for (int c = 0; c < CC; ++c) {
            #pragma unroll
            for (int kd = 0; kd < 3; ++kd)
            #pragma unroll
            for (int kh = 0; kh < 3; ++kh) {
                // 6-wide duplicated input windows: one LDS.64 each
                uint64_t bcast[2][6];
                #pragma unroll
                for (int i = 0; i < 2; ++i) {
                    const int dhi = dh2 * 2 + i;
                    const int dl = dhi >> 2, hl = dhi & 3;
                    const float2* bp =
                        &s_in2[c * SIN_C + (dl + kd) * SIN_H + (hl + kh) * SW_ROW + wb];
                    #pragma unroll
                    for (int j = 0; j < 6; ++j)
                        bcast[i][j] = *reinterpret_cast<const uint64_t*>(bp + j);
                }
                #pragma unroll
                for (int kw = 0; kw < 3; ++kw) {
                    const int k = (kd * 3 + kh) * 3 + kw;
                    #pragma unroll
                    for (int op = 0; op < 4; ++op) {
                        uint64_t wp = *reinterpret_cast<const uint64_t*>(
                            &s_w[(c * 27 + k) * 32 + cob + 2 * op]);
                        #pragma unroll
                        for (int i = 0; i < 2; ++i)
                            #pragma unroll
                            for (int j = 0; j < 4; ++j)
                                FFMA2(acc2[i][op][j], bcast[i][kw + j], wp);
                    }
                }
            }
        }
        __syncthreads();
    }

    // epilogue: BN + ReLU, float4 stores per output channel
    #pragma unroll
    for (int op = 0; op < 4; ++op) {
        const int co0 = cob + 2 * op;
        const float inv0 = gamma[co0] * rsqrtf(var[co0] + 1e-5f);
        const float sh0  = beta[co0] - mean[co0] * inv0;
        const float inv1 = gamma[co0+1] * rsqrtf(var[co0+1] + 1e-5f);
        const float sh1  = beta[co0+1] - mean[co0+1] * inv1;
        #pragma unroll
        for (int i = 0; i < 2; ++i) {
            const int dhi = dh2 * 2 + i;
            const int dl = dhi >> 2, hl = dhi & 3;
            float lo[4], hi[4];
            #pragma unroll
            for (int j = 0; j < 4; ++j) UNPACK2(lo[j], hi[j], acc2[i][op][j]);
            float4 v0, v1;
            v0.x = fmaxf(lo[0]*inv0+sh0, 0.f); v0.y = fmaxf(lo[1]*inv0+sh0, 0.f);
            v0.z = fmaxf(lo[2]*inv0+sh0, 0.f); v0.w = fmaxf(lo[3]*inv0+sh0, 0.f);
            v1.x = fmaxf(hi[0]*inv1+sh1, 0.f); v1.y = fmaxf(hi[1]*inv1+sh1, 0.f);
            v1.z = fmaxf(hi[2]*inv1+sh1, 0.f); v1.w = fmaxf(hi[3]*inv1+sh1, 0.f);
            size_t o0 = (((size_t)(b * CO + co0)   * DD_ + d0 + dl) * HH_ + h0 + hl) * WW_ + w0 + wb;
            size_t o1 = (((size_t)(b * CO + co0+1) * DD_ + d0 + dl) * HH_ + h0 + hl) * WW_ + w0 + wb;
            *reinterpret_cast<float4*>(out + o0) = v0;
            *reinterpret_cast<float4*>(out + o1) = v1;
        }
    }
}

// ---------------------------------------------------------------------------

extern "C" void kernel_launch(void* const* d_in, const int* in_sizes, int n_in,
                              void* d_out, int out_size)
{
    const float* lg = (const float*)d_in[0];
    const float* rg = (const float*)d_in[1];
    const float* lc = (const float*)d_in[2];
    const float* rc = (const float*)d_in[3];
    const float* w1 = (const float*)d_in[4];
    const float* g1 = (const float*)d_in[5];
    const float* b1 = (const float*)d_in[6];
    const float* m1 = (const float*)d_in[7];
    const float* v1 = (const float*)d_in[8];
    const float* w2 = (const float*)d_in[9];
    const float* g2 = (const float*)d_in[10];
    const float* b2 = (const float*)d_in[11];
    const float* m2 = (const float*)d_in[12];
    const float* v2 = (const float*)d_in[13];
    float* out = (float*)d_out;

    float* vol = nullptr;
    float* x1  = nullptr;
    cudaGetSymbolAddress((void**)&vol, g_vol);
    cudaGetSymbolAddress((void**)&x1,  g_x1);

    // allow >48KB dynamic smem (idempotent)
    cudaFuncSetAttribute(conv3d_bn_relu<CIN1>,
                         cudaFuncAttributeMaxDynamicSharedMemorySize, SMEM_TOTAL_CONV);
    cudaFuncSetAttribute(conv3d_bn_relu<CO>,
                         cudaFuncAttributeMaxDynamicSharedMemorySize, SMEM_TOTAL_CONV);

    // 1) cost volume
    dim3 gv(BB * HH_, 11);
    build_volume_kernel<<<gv, 256>>>(lg, rg, lc, rc);

    // 2) conv1 + BN + ReLU (64 -> 32), split in two launches so ncu's
    //    skip-5/capture-1 window lands on a conv kernel.
    dim3 gridA(4, 16, 24);
    conv3d_bn_relu<CIN1><<<gridA, 256, SMEM_TOTAL_CONV>>>(vol, w1, g1, b1, m1, v1, x1, 0);
    conv3d_bn_relu<CIN1><<<gridA, 256, SMEM_TOTAL_CONV>>>(vol, w1, g1, b1, m1, v1, x1, 24);

    // 3) conv2 + BN + ReLU (32 -> 32)
    dim3 grid2(4, 16, BB * 12);
    conv3d_bn_relu<CO><<<grid2, 256, SMEM_TOTAL_CONV>>>(x1, w2, g2, b2, m2, v2, out, 0);
}

// round 13
// speedup vs baseline: 2.7714x; 2.7714x over previous
#include <cuda_runtime.h>
#include <cuda_bf16.h>
#include <cstdint>

#define NG      40
#define CPG     8
#define CCH     12
#define BB      4
#define HH_     64
#define WW_     128
#define DD_     48
#define HW      (HH_*WW_)         /* 8192 */
#define DHW     ((size_t)DD_*HW)  /* 393216 */

// Scratch (device globals — no allocation APIs)
__device__ float g_vol[(size_t)BB*64*DD_*HH_*WW_];
__device__ float g_x1 [(size_t)BB*32*DD_*HH_*WW_];
// B fragments: [tap 27][pass 2][ks 4][nt 4][lane 32] as uint2 (mma b0,b1)
__device__ uint2 g_bf1[27*2*16*32];
__device__ uint2 g_bf2[27*2*16*32];

__device__ __forceinline__ uint32_t smem_u32(const void* p) {
    uint32_t a;
    asm("{ .reg .u64 t; cvta.to.shared.u64 t, %1; cvt.u32.u64 %0, t; }" : "=r"(a) : "l"(p));
    return a;
}

#define MMA16816(c0,c1,c2,c3, a0,a1,a2,a3, b0,b1) \
    asm volatile("mma.sync.aligned.m16n8k16.row.col.f32.bf16.bf16.f32 " \
        "{%0,%1,%2,%3}, {%4,%5,%6,%7}, {%8,%9}, {%0,%1,%2,%3};" \
        : "+f"(c0),"+f"(c1),"+f"(c2),"+f"(c3) \
        : "r"(a0),"r"(a1),"r"(a2),"r"(a3),"r"(b0),"r"(b1))

#define LDSM4(r0,r1,r2,r3, a) \
    asm volatile("ldmatrix.sync.aligned.m8n8.x4.shared.b16 {%0,%1,%2,%3}, [%4];" \
        : "=r"(r0),"=r"(r1),"=r"(r2),"=r"(r3) : "r"(a))

// ---------------------------------------------------------------------------
// Kernel 1: build cost volume (unchanged — 148us, HBM-bound)
// ---------------------------------------------------------------------------
__global__ __launch_bounds__(256)
void build_volume_kernel(const float* __restrict__ lg,
                         const float* __restrict__ rg,
                         const float* __restrict__ lc,
                         const float* __restrict__ rc)
{
    __shared__ float lgs[32][WW_];
    __shared__ float rgs[32][WW_];

    const int b     = blockIdx.x / HH_;
    const int h     = blockIdx.x % HH_;
    const int chunk = blockIdx.y;
    const int tid   = threadIdx.x;
    const int w     = tid & 127;
    const int t2    = tid >> 7;

    if (chunk < 10) {
        for (int i = tid; i < 32 * WW_; i += 256) {
            int ch = i >> 7, ww = i & 127;
            int cg = chunk * 32 + ch;
            lgs[ch][ww] = lg[((size_t)(b * 320 + cg) * HH_ + h) * WW_ + ww];
            rgs[ch][ww] = rg[((size_t)(b * 320 + cg) * HH_ + h) * WW_ + ww];
        }
        __syncthreads();
        for (int gi = 0; gi < 2; ++gi) {
            int g = t2 + gi * 2;
            float lreg[CPG];
            #pragma unroll
            for (int c = 0; c < CPG; ++c) lreg[c] = lgs[g * CPG + c][w];
            int gout = chunk * 4 + g;
            float* outp = g_vol + (size_t)(b * 64 + gout) * DHW + (size_t)h * WW_ + w;
            #pragma unroll 4
            for (int d = 0; d < DD_; ++d) {
                float v = 0.f;
                if (w >= d) {
                    float s = 0.f;
                    #pragma unroll
                    for (int c = 0; c < CPG; ++c)
                        s += lreg[c] * rgs[g * CPG + c][w - d];
                    v = s * (1.0f / CPG);
                }
                outp[(size_t)d * HW] = v;
            }
        }
    } else {
        for (int i = tid; i < 24 * WW_; i += 256) {
            int ch = i >> 7, ww = i & 127;
            lgs[ch][ww] = (ch < 12)
                ? lc[((size_t)(b * CCH + ch)      * HH_ + h) * WW_ + ww]
                : rc[((size_t)(b * CCH + (ch-12)) * HH_ + h) * WW_ + ww];
        }
        __syncthreads();
        for (int idx = t2; idx < 24 * DD_; idx += 2) {
            int ch = idx / DD_, d = idx % DD_;
            float v = 0.f;
            if (w >= d) v = (ch < 12) ? lgs[ch][w] : lgs[ch][w - d];
            g_vol[(size_t)(b * 64 + 40 + ch) * DHW + (size_t)d * HW + (size_t)h * WW_ + w] = v;
        }
    }
}

// ---------------------------------------------------------------------------
// Kernel 1b: prepack weights into per-lane mma B fragments, bf16 hi/lo.
//   Fragment (m16n8k16, B col 16x8): b0={B[2t][g],B[2t+1][g]}, b1={B[2t+8][g],B[2t+9][g]}
//   with t=lane&3, g=lane>>2; B[k][n] = w[co=n][ci=k] for the tap.
// ---------------------------------------------------------------------------
__global__ void prepack_w(const float* __restrict__ w1, const float* __restrict__ w2)
{
    const int tap = blockIdx.x;   // 0..26
    for (int e = threadIdx.x; e < 1024; e += 256) {
        const int pass = e >> 9;          // 0 hi, 1 lo
        const int ks   = (e >> 7) & 3;
        const int nt   = (e >> 5) & 3;
        const int lane = e & 31;
        const int t4 = lane & 3, gg = lane >> 2;
        const int co = nt * 8 + gg;
        const int k0 = ks * 16 + t4 * 2;
        const int kk[4] = {k0, k0 + 1, k0 + 8, k0 + 9};
        const size_t idx = (((size_t)tap * 2 + pass) * 16 + ks * 4 + nt) * 32 + lane;
        {
            uint16_t u[4];
            #pragma unroll
            for (int i = 0; i < 4; ++i) {
                float f = w1[((size_t)co * 64 + kk[i]) * 27 + tap];
                __nv_bfloat16 hi = __float2bfloat16(f);
                u[i] = (pass == 0) ? __bfloat16_as_ushort(hi)
                     : __bfloat16_as_ushort(__float2bfloat16(f - __bfloat162float(hi)));
            }
            uint2 r;
            r.x = ((uint32_t)u[1] << 16) | u[0];
            r.y = ((uint32_t)u[3] << 16) | u[2];
            g_bf1[idx] = r;
        }
        {
            uint16_t u[4];
            #pragma unroll
            for (int i = 0; i < 4; ++i) {
                float f = (kk[i] < 32) ? w2[((size_t)co * 32 + kk[i]) * 27 + tap] : 0.f;
                __nv_bfloat16 hi = __float2bfloat16(f);
                u[i] = (pass == 0) ? __bfloat16_as_ushort(hi)
                     : __bfloat16_as_ushort(__float2bfloat16(f - __bfloat162float(hi)));
            }
            uint2 r;
            r.x = ((uint32_t)u[1] << 16) | u[0];
            r.y = ((uint32_t)u[3] << 16) | u[2];
            g_bf2[idx] = r;
        }
    }
}

// ---------------------------------------------------------------------------
// Kernel 2/3: conv3d 3x3x3 + BN + ReLU via mma.sync (HMMA) bf16 hi/lo 3-pass.
//   CTA = one (b,d,h) row. M=128 w (8 warps x m16), N=32 co (4 n8), K=ci/tap.
//   A in smem [w+1][ci] bf16 (hi & lo buffers, padded row stride ROWB bytes);
//   kw shift = +-1 row on the ldmatrix base. Edge rows 0/129 stay zero.
// ---------------------------------------------------------------------------
template<int CI, int KSTEPS, int ROWB>
__global__ __launch_bounds__(256, 2)
void conv_mma(const float* __restrict__ in, const uint2* __restrict__ bfrag,
              const float* __restrict__ gamma, const float* __restrict__ beta,
              const float* __restrict__ mean, const float* __restrict__ var,
              float* __restrict__ out, int bz)
{
    __shared__ __align__(16) uint8_t smA[2][130 * ROWB];
    __shared__ float2 s_bn[32];

    const int h = blockIdx.x, d = blockIdx.y, b = blockIdx.z + bz;
    const int tid = threadIdx.x, wid = tid >> 5, lane = tid & 31;
    const int g = lane >> 2, t4 = lane & 3;

    // zero edge rows (w=-1 -> row 0, w=128 -> row 129) in both buffers
    {
        const int nw = ROWB / 4;
        if (tid < 4 * nw) {
            int r = tid / nw, wd = tid % nw;
            int buf = r >> 1, row = (r & 1) ? 129 : 0;
            *(uint32_t*)&smA[buf][row * ROWB + wd * 4] = 0u;
        }
    }
    if (tid < 32) {
        float iv = gamma[tid] * rsqrtf(var[tid] + 1e-5f);
        s_bn[tid] = make_float2(iv, beta[tid] - mean[tid] * iv);
    }
    __syncthreads();

    // per-lane ldmatrix address offset (x4: lanes 0-7 m0 rows, 8-15 m1(+8),
    // 16-23 m2(cols+8), 24-31 m3)
    const int lj = lane >> 3, lr = lane & 7;
    const uint32_t aoffs = (uint32_t)((wid * 16 + (lj & 1) * 8 + lr) * ROWB + (lj >> 1) * 16);
    const uint32_t baseHi = smem_u32(&smA[0][0]);
    const uint32_t baseLo = smem_u32(&smA[1][0]);

    float acc[4][4];
    #pragma unroll
    for (int nt = 0; nt < 4; ++nt)
        #pragma unroll
        for (int i = 0; i < 4; ++i) acc[nt][i] = 0.f;

    // fill assignment: thread owns one w column, 32 ci values
    const int wcol = tid & 127;
    const int half = tid >> 7;           // conv1: 0/1 -> ci 0-31 / 32-63
    const bool active = (half * 32 < CI);
    const int ci0 = half * 32;

    for (int kd = 0; kd < 3; ++kd) {
        const int id = d + kd - 1;
        if (id < 0 || id >= DD_) continue;
        for (int kh = 0; kh < 3; ++kh) {
            const int ih = h + kh - 1;
            if (ih < 0 || ih >= HH_) continue;

            // ---- load + convert (registers only; overlaps other warps' mma) ----
            uint2 pH[8], pL[8];
            if (active) {
                float fv[32];
                const float* pin = in + ((size_t)(b * CI + ci0) * DD_ + id) * ((size_t)HH_ * WW_)
                                      + (size_t)ih * WW_ + wcol;
                #pragma unroll
                for (int c = 0; c < 32; ++c) fv[c] = pin[(size_t)c * DHW];
                #pragma unroll
                for (int q = 0; q < 8; ++q) {
                    uint16_t uh[4], ul[4];
                    #pragma unroll
                    for (int i = 0; i < 4; ++i) {
                        float f = fv[q * 4 + i];
                        __nv_bfloat16 hi = __float2bfloat16(f);
                        uh[i] = __bfloat16_as_ushort(hi);
                        ul[i] = __bfloat16_as_ushort(__float2bfloat16(f - __bfloat162float(hi)));
                    }
                    pH[q].x = ((uint32_t)uh[1] << 16) | uh[0];
                    pH[q].y = ((uint32_t)uh[3] << 16) | uh[2];
                    pL[q].x = ((uint32_t)ul[1] << 16) | ul[0];
                    pL[q].y = ((uint32_t)ul[3] << 16) | ul[2];
                }
            }
            __syncthreads();   // previous stage's mma reads done before overwrite
            if (active) {
                const uint32_t rowoff = (uint32_t)((wcol + 1) * ROWB + ci0 * 2);
                #pragma unroll
                for (int q = 0; q < 8; ++q) {
                    *(uint2*)&smA[0][rowoff + 8 * q] = pH[q];
                    *(uint2*)&smA[1][rowoff + 8 * q] = pL[q];
                }
            }
            __syncthreads();

            // ---- compute: 3 kw x KSTEPS x 4 ntiles x 3 passes ----
            #pragma unroll
            for (int kw = 0; kw < 3; ++kw) {
                const int tap = kd * 9 + kh * 3 + kw;
                const uint2* bp = bfrag + (size_t)tap * 1024;   // [pass 512][ks*4+nt]*32+lane
                uint2 Bh[KSTEPS][4], Bl[KSTEPS][4];
                #pragma unroll
                for (int ks = 0; ks < KSTEPS; ++ks)
                    #pragma unroll
                    for (int nt = 0; nt < 4; ++nt) {
                        Bh[ks][nt] = bp[(ks * 4 + nt) * 32 + lane];
                        Bl[ks][nt] = bp[512 + (ks * 4 + nt) * 32 + lane];
                    }
                #pragma unroll
                for (int ks = 0; ks < KSTEPS; ++ks) {
                    const uint32_t ad = aoffs + (uint32_t)(kw * ROWB + ks * 32);
                    uint32_t ah0, ah1, ah2, ah3, al0, al1, al2, al3;
                    LDSM4(ah0, ah1, ah2, ah3, baseHi + ad);
                    LDSM4(al0, al1, al2, al3, baseLo + ad);
                    #pragma unroll
                    for (int nt = 0; nt < 4; ++nt) {
                        MMA16816(acc[nt][0], acc[nt][1], acc[nt][2], acc[nt][3],
                                 ah0, ah1, ah2, ah3, Bh[ks][nt].x, Bh[ks][nt].y);
                        MMA16816(acc[nt][0], acc[nt][1], acc[nt][2], acc[nt][3],
                                 ah0, ah1, ah2, ah3, Bl[ks][nt].x, Bl[ks][nt].y);
                        MMA16816(acc[nt][0], acc[nt][1], acc[nt][2], acc[nt][3],
                                 al0, al1, al2, al3, Bh[ks][nt].x, Bh[ks][nt].y);
                    }
                }
            }
        }
    }

    // ---- epilogue: BN + ReLU, direct STG ----
    const int wm = wid * 16 + g;
    float* ob = out + (size_t)(b * 32) * DHW + (size_t)d * HW + (size_t)h * WW_;
    #pragma unroll
    for (int nt = 0; nt < 4; ++nt) {
        const int co = nt * 8 + t4 * 2;
        float2 bn0 = s_bn[co], bn1 = s_bn[co + 1];
        ob[(size_t)co * DHW + wm]           = fmaxf(acc[nt][0] * bn0.x + bn0.y, 0.f);
        ob[(size_t)(co + 1) * DHW + wm]     = fmaxf(acc[nt][1] * bn1.x + bn1.y, 0.f);
        ob[(size_t)co * DHW + wm + 8]       = fmaxf(acc[nt][2] * bn0.x + bn0.y, 0.f);
        ob[(size_t)(co + 1) * DHW + wm + 8] = fmaxf(acc[nt][3] * bn1.x + bn1.y, 0.f);
    }
}

// ---------------------------------------------------------------------------

extern "C" void kernel_launch(void* const* d_in, const int* in_sizes, int n_in,
                              void* d_out, int out_size)
{
    const float* lg = (const float*)d_in[0];
    const float* rg = (const float*)d_in[1];
    const float* lc = (const float*)d_in[2];
    const float* rc = (const float*)d_in[3];
    const float* w1 = (const float*)d_in[4];
    const float* g1 = (const float*)d_in[5];
    const float* b1 = (const float*)d_in[6];
    const float* m1 = (const float*)d_in[7];
    const float* v1 = (const float*)d_in[8];
    const float* w2 = (const float*)d_in[9];
    const float* g2 = (const float*)d_in[10];
    const float* b2 = (const float*)d_in[11];
    const float* m2 = (const float*)d_in[12];
    const float* v2 = (const float*)d_in[13];
    float* out = (float*)d_out;

    float* vol = nullptr; float* x1 = nullptr;
    uint2* bf1 = nullptr; uint2* bf2 = nullptr;
    cudaGetSymbolAddress((void**)&vol, g_vol);
    cudaGetSymbolAddress((void**)&x1,  g_x1);
    cudaGetSymbolAddress((void**)&bf1, g_bf1);
    cudaGetSymbolAddress((void**)&bf2, g_bf2);

    // 1) cost volume
    dim3 gv(BB * HH_, 11);
    build_volume_kernel<<<gv, 256>>>(lg, rg, lc, rc);

    // 1b) weight prepack into mma fragments
    prepack_w<<<27, 256>>>(w1, w2);

    // 2) conv1 (64->32), split by batch so ncu's skip-5 capture lands on it
    dim3 gc(HH_, DD_, 1);
    conv_mma<64, 4, 144><<<gc, 256>>>(vol, bf1, g1, b1, m1, v1, x1, 0);
    conv_mma<64, 4, 144><<<gc, 256>>>(vol, bf1, g1, b1, m1, v1, x1, 1);
    conv_mma<64, 4, 144><<<gc, 256>>>(vol, bf1, g1, b1, m1, v1, x1, 2);
    conv_mma<64, 4, 144><<<gc, 256>>>(vol, bf1, g1, b1, m1, v1, x1, 3);

    // 3) conv2 (32->32)
    dim3 gc2(HH_, DD_, BB);
    conv_mma<32, 2, 80><<<gc2, 256>>>(x1, bf2, g2, b2, m2, v2, out, 0);
}

// round 15
// speedup vs baseline: 3.7079x; 1.3379x over previous
#include <cuda_runtime.h>
#include <cuda_bf16.h>
#include <cstdint>

#define NG      40
#define CPG     8
#define CCH     12
#define BB      4
#define HH_     64
#define WW_     128
#define DD_     48
#define HW      (HH_*WW_)         /* 8192 */
#define DHW     ((size_t)DD_*HW)  /* 393216 */

// Scratch (device globals — no allocation APIs)
__device__ float g_vol[(size_t)BB*64*DD_*HH_*WW_];
__device__ float g_x1 [(size_t)BB*32*DD_*HH_*WW_];
// B fragments: [tap 27][ks 4][nt 4][lane 32] uint4 = {bh0,bh1,bl0,bl1}
__device__ uint4 g_bf1[27*16*32];
__device__ uint4 g_bf2[27*16*32];

__device__ __forceinline__ uint32_t smem_u32(const void* p) {
    uint32_t a;
    asm("{ .reg .u64 t; cvta.to.shared.u64 t, %1; cvt.u32.u64 %0, t; }" : "=r"(a) : "l"(p));
    return a;
}

#define MMA16816(c0,c1,c2,c3, a0,a1,a2,a3, b0,b1) \
    asm volatile("mma.sync.aligned.m16n8k16.row.col.f32.bf16.bf16.f32 " \
        "{%0,%1,%2,%3}, {%4,%5,%6,%7}, {%8,%9}, {%0,%1,%2,%3};" \
        : "+f"(c0),"+f"(c1),"+f"(c2),"+f"(c3) \
        : "r"(a0),"r"(a1),"r"(a2),"r"(a3),"r"(b0),"r"(b1))

#define LDSM4(r0,r1,r2,r3, a) \
    asm volatile("ldmatrix.sync.aligned.m8n8.x4.shared.b16 {%0,%1,%2,%3}, [%4];" \
        : "=r"(r0),"=r"(r1),"=r"(r2),"=r"(r3) : "r"(a))

// ---------------------------------------------------------------------------
// Kernel 1: build cost volume (unchanged — 148us, HBM-bound)
// ---------------------------------------------------------------------------
__global__ __launch_bounds__(256)
void build_volume_kernel(const float* __restrict__ lg,
                         const float* __restrict__ rg,
                         const float* __restrict__ lc,
                         const float* __restrict__ rc)
{
    __shared__ float lgs[32][WW_];
    __shared__ float rgs[32][WW_];

    const int b     = blockIdx.x / HH_;
    const int h     = blockIdx.x % HH_;
    const int chunk = blockIdx.y;
    const int tid   = threadIdx.x;
    const int w     = tid & 127;
    const int t2    = tid >> 7;

    if (chunk < 10) {
        for (int i = tid; i < 32 * WW_; i += 256) {
            int ch = i >> 7, ww = i & 127;
            int cg = chunk * 32 + ch;
            lgs[ch][ww] = lg[((size_t)(b * 320 + cg) * HH_ + h) * WW_ + ww];
            rgs[ch][ww] = rg[((size_t)(b * 320 + cg) * HH_ + h) * WW_ + ww];
        }
        __syncthreads();
        for (int gi = 0; gi < 2; ++gi) {
            int g = t2 + gi * 2;
            float lreg[CPG];
            #pragma unroll
            for (int c = 0; c < CPG; ++c) lreg[c] = lgs[g * CPG + c][w];
            int gout = chunk * 4 + g;
            float* outp = g_vol + (size_t)(b * 64 + gout) * DHW + (size_t)h * WW_ + w;
            #pragma unroll 4
            for (int d = 0; d < DD_; ++d) {
                float v = 0.f;
                if (w >= d) {
                    float s = 0.f;
                    #pragma unroll
                    for (int c = 0; c < CPG; ++c)
                        s += lreg[c] * rgs[g * CPG + c][w - d];
                    v = s * (1.0f / CPG);
                }
                outp[(size_t)d * HW] = v;
            }
        }
    } else {
        for (int i = tid; i < 24 * WW_; i += 256) {
            int ch = i >> 7, ww = i & 127;
            lgs[ch][ww] = (ch < 12)
                ? lc[((size_t)(b * CCH + ch)      * HH_ + h) * WW_ + ww]
                : rc[((size_t)(b * CCH + (ch-12)) * HH_ + h) * WW_ + ww];
        }
        __syncthreads();
        for (int idx = t2; idx < 24 * DD_; idx += 2) {
            int ch = idx / DD_, d = idx % DD_;
            float v = 0.f;
            if (w >= d) v = (ch < 12) ? lgs[ch][w] : lgs[ch][w - d];
            g_vol[(size_t)(b * 64 + 40 + ch) * DHW + (size_t)d * HW + (size_t)h * WW_ + w] = v;
        }
    }
}

// ---------------------------------------------------------------------------
// Kernel 1b: prepack weights into per-lane mma B fragments (uint4: hi|lo).
//   m16n8k16 B col frag: b0={B[2t][g],B[2t+1][g]}, b1={B[2t+8][g],B[2t+9][g]},
//   t=lane&3, g=lane>>2; B[k][n] = w[co=n][ci=k].
// ---------------------------------------------------------------------------
__global__ void prepack_w(const float* __restrict__ w1, const float* __restrict__ w2)
{
    const int tap = blockIdx.x;   // 0..26
    for (int e = threadIdx.x; e < 512; e += 256) {
        const int ks   = e >> 7;
        const int nt   = (e >> 5) & 3;
        const int lane = e & 31;
        const int t4 = lane & 3, gg = lane >> 2;
        const int co = nt * 8 + gg;
        const int k0 = ks * 16 + t4 * 2;
        const int kk[4] = {k0, k0 + 1, k0 + 8, k0 + 9};
        const size_t idx = ((size_t)tap * 16 + ks * 4 + nt) * 32 + lane;
        {
            uint16_t uh[4], ul[4];
            #pragma unroll
            for (int i = 0; i < 4; ++i) {
                float f = w1[((size_t)co * 64 + kk[i]) * 27 + tap];
                __nv_bfloat16 hi = __float2bfloat16(f);
                uh[i] = __bfloat16_as_ushort(hi);
                ul[i] = __bfloat16_as_ushort(__float2bfloat16(f - __bfloat162float(hi)));
            }
            uint4 r;
            r.x = ((uint32_t)uh[1] << 16) | uh[0];
            r.y = ((uint32_t)uh[3] << 16) | uh[2];
            r.z = ((uint32_t)ul[1] << 16) | ul[0];
            r.w = ((uint32_t)ul[3] << 16) | ul[2];
            g_bf1[idx] = r;
        }
        {
            uint16_t uh[4], ul[4];
            #pragma unroll
            for (int i = 0; i < 4; ++i) {
                float f = (kk[i] < 32) ? w2[((size_t)co * 32 + kk[i]) * 27 + tap] : 0.f;
                __nv_bfloat16 hi = __float2bfloat16(f);
                uh[i] = __bfloat16_as_ushort(hi);
                ul[i] = __bfloat16_as_ushort(__float2bfloat16(f - __bfloat162float(hi)));
            }
            uint4 r;
            r.x = ((uint32_t)uh[1] << 16) | uh[0];
            r.y = ((uint32_t)uh[3] << 16) | uh[2];
            r.z = ((uint32_t)ul[1] << 16) | ul[0];
            r.w = ((uint32_t)ul[3] << 16) | ul[2];
            g_bf2[idx] = r;
        }
    }
}

// ---------------------------------------------------------------------------
// Kernel 2/3: conv3d 3x3x3 + BN + ReLU via mma.sync bf16 hi/lo 3-pass.
//   128 threads / 4 warps; per-warp M=32 (two m16 frags) -> B fragment loads
//   amortized over 2x M (half the B L1 wavefronts vs 8-warp version).
//   A in smem [w+1][ci] bf16 hi&lo buffers, row stride ROWB; kw = +-1 row shift.
// ---------------------------------------------------------------------------
template<int CI, int KSTEPS, int ROWB>
__global__ __launch_bounds__(128)
void conv_mma(const float* __restrict__ in, const uint4* __restrict__ bfrag,
              const float* __restrict__ gamma, const float* __restrict__ beta,
              const float* __restrict__ mean, const float* __restrict__ var,
              float* __restrict__ out, int bz)
{
    __shared__ __align__(16) uint8_t smA[2][130 * ROWB];
    __shared__ float2 s_bn[32];

    const int h = blockIdx.x, d = blockIdx.y, b = blockIdx.z + bz;
    const int tid = threadIdx.x, wid = tid >> 5, lane = tid & 31;
    const int g = lane >> 2, t4 = lane & 3;

    // zero edge rows (w=-1 -> row 0, w=128 -> row 129) in both buffers
    for (int i = tid; i < 4 * (ROWB / 4); i += 128) {
        const int nw = ROWB / 4;
        int r = i / nw, wd = i % nw;
        int buf = r >> 1, row = (r & 1) ? 129 : 0;
        *(uint32_t*)&smA[buf][row * ROWB + wd * 4] = 0u;
    }
    if (tid < 32) {
        float iv = gamma[tid] * rsqrtf(var[tid] + 1e-5f);
        s_bn[tid] = make_float2(iv, beta[tid] - mean[tid] * iv);
    }
    __syncthreads();

    // ldmatrix x4 per-lane offset (m-frag base added later)
    const int lj = lane >> 3, lr = lane & 7;
    const uint32_t aoff0 = (uint32_t)((wid * 32 + (lj & 1) * 8 + lr) * ROWB + (lj >> 1) * 16);
    const uint32_t baseHi = smem_u32(&smA[0][0]);
    const uint32_t baseLo = smem_u32(&smA[1][0]);

    float acc[2][4][4];    // [m-frag][ntile][4]
    #pragma unroll
    for (int mf = 0; mf < 2; ++mf)
        #pragma unroll
        for (int nt = 0; nt < 4; ++nt)
            #pragma unroll
            for (int i = 0; i < 4; ++i) acc[mf][nt][i] = 0.f;

    const int wcol = tid;    // thread owns one w column
    const uint32_t rowbase = (uint32_t)((wcol + 1) * ROWB);

    for (int kd = 0; kd < 3; ++kd) {
        const int id = d + kd - 1;
        if (id < 0 || id >= DD_) continue;
        for (int kh = 0; kh < 3; ++kh) {
            const int ih = h + kh - 1;
            if (ih < 0 || ih >= HH_) continue;

            // ---- prefetch first ci-half into regs (overlaps prior mma) ----
            uint2 pH[8], pL[8];
            {
                const float* pin = in + ((size_t)(b * CI) * DD_ + id) * ((size_t)HH_ * WW_)
                                      + (size_t)ih * WW_ + wcol;
                float fv[32];
                #pragma unroll
                for (int c = 0; c < 32; ++c) fv[c] = pin[(size_t)c * DHW];
                #pragma unroll
                for (int q = 0; q < 8; ++q) {
                    uint16_t uh[4], ul[4];
                    #pragma unroll
                    for (int i = 0; i < 4; ++i) {
                        float f = fv[q * 4 + i];
                        __nv_bfloat16 hi = __float2bfloat16(f);
                        uh[i] = __bfloat16_as_ushort(hi);
                        ul[i] = __bfloat16_as_ushort(__float2bfloat16(f - __bfloat162float(hi)));
                    }
                    pH[q].x = ((uint32_t)uh[1] << 16) | uh[0];
                    pH[q].y = ((uint32_t)uh[3] << 16) | uh[2];
                    pL[q].x = ((uint32_t)ul[1] << 16) | ul[0];
                    pL[q].y = ((uint32_t)ul[3] << 16) | ul[2];
                }
            }
            __syncthreads();   // prior stage's mma reads done before overwrite
            #pragma unroll
            for (int q = 0; q < 8; ++q) {
                *(uint2*)&smA[0][rowbase + 8 * q] = pH[q];
                *(uint2*)&smA[1][rowbase + 8 * q] = pL[q];
            }
            if (CI == 64) {  // second ci-half
                const float* pin = in + ((size_t)(b * CI + 32) * DD_ + id) * ((size_t)HH_ * WW_)
                                      + (size_t)ih * WW_ + wcol;
                float fv[32];
                #pragma unroll
                for (int c = 0; c < 32; ++c) fv[c] = pin[(size_t)c * DHW];
                #pragma unroll
                for (int q = 0; q < 8; ++q) {
                    uint16_t uh[4], ul[4];
                    #pragma unroll
                    for (int i = 0; i < 4; ++i) {
                        float f = fv[q * 4 + i];
                        __nv_bfloat16 hi = __float2bfloat16(f);
                        uh[i] = __bfloat16_as_ushort(hi);
                        ul[i] = __bfloat16_as_ushort(__float2bfloat16(f - __bfloat162float(hi)));
                    }
                    uint2 a, c2;
                    a.x  = ((uint32_t)uh[1] << 16) | uh[0];
                    a.y  = ((uint32_t)uh[3] << 16) | uh[2];
                    c2.x = ((uint32_t)ul[1] << 16) | ul[0];
                    c2.y = ((uint32_t)ul[3] << 16) | ul[2];
                    *(uint2*)&smA[0][rowbase + 64 + 8 * q] = a;
                    *(uint2*)&smA[1][rowbase + 64 + 8 * q] = c2;
                }
            }
            __syncthreads();

            // ---- compute: 3 kw x KSTEPS x (2 mf x 4 nt x 3 passes) ----
            #pragma unroll
            for (int kw = 0; kw < 3; ++kw) {
                const int tap = kd * 9 + kh * 3 + kw;
                const uint4* bp = bfrag + (size_t)tap * 512 + lane;
                #pragma unroll
                for (int ks = 0; ks < KSTEPS; ++ks) {
                    uint4 Bv[4];
                    #pragma unroll
                    for (int nt = 0; nt < 4; ++nt)
                        Bv[nt] = bp[(ks * 4 + nt) * 32];
                    const uint32_t ad = aoff0 + (uint32_t)(kw * ROWB + ks * 32);
                    #pragma unroll
                    for (int mf = 0; mf < 2; ++mf) {
                        const uint32_t adm = ad + (uint32_t)(mf * 16 * ROWB);
                        uint32_t ah0, ah1, ah2, ah3, al0, al1, al2, al3;
                        LDSM4(ah0, ah1, ah2, ah3, baseHi + adm);
                        LDSM4(al0, al1, al2, al3, baseLo + adm);
                        #pragma unroll
                        for (int nt = 0; nt < 4; ++nt) {
                            MMA16816(acc[mf][nt][0], acc[mf][nt][1], acc[mf][nt][2], acc[mf][nt][3],
                                     ah0, ah1, ah2, ah3, Bv[nt].x, Bv[nt].y);
                            MMA16816(acc[mf][nt][0], acc[mf][nt][1], acc[mf][nt][2], acc[mf][nt][3],
                                     ah0, ah1, ah2, ah3, Bv[nt].z, Bv[nt].w);
                            MMA16816(acc[mf][nt][0], acc[mf][nt][1], acc[mf][nt][2], acc[mf][nt][3],
                                     al0, al1, al2, al3, Bv[nt].x, Bv[nt].y);
                        }
                    }
                }
            }
        }
    }

    // ---- epilogue: BN + ReLU, direct STG ----
    float* ob = out + (size_t)(b * 32) * DHW + (size_t)d * HW + (size_t)h * WW_;
    #pragma unroll
    for (int mf = 0; mf < 2; ++mf) {
        const int wm = wid * 32 + mf * 16 + g;
        #pragma unroll
        for (int nt = 0; nt < 4; ++nt) {
            const int co = nt * 8 + t4 * 2;
            float2 bn0 = s_bn[co], bn1 = s_bn[co + 1];
            ob[(size_t)co * DHW + wm]           = fmaxf(acc[mf][nt][0] * bn0.x + bn0.y, 0.f);
            ob[(size_t)(co + 1) * DHW + wm]     = fmaxf(acc[mf][nt][1] * bn1.x + bn1.y, 0.f);
            ob[(size_t)co * DHW + wm + 8]       = fmaxf(acc[mf][nt][2] * bn0.x + bn0.y, 0.f);
            ob[(size_t)(co + 1) * DHW + wm + 8] = fmaxf(acc[mf][nt][3] * bn1.x + bn1.y, 0.f);
        }
    }
}

// ---------------------------------------------------------------------------

extern "C" void kernel_launch(void* const* d_in, const int* in_sizes, int n_in,
                              void* d_out, int out_size)
{
    const float* lg = (const float*)d_in[0];
    const float* rg = (const float*)d_in[1];
    const float* lc = (const float*)d_in[2];
    const float* rc = (const float*)d_in[3];
    const float* w1 = (const float*)d_in[4];
    const float* g1 = (const float*)d_in[5];
    const float* b1 = (const float*)d_in[6];
    const float* m1 = (const float*)d_in[7];
    const float* v1 = (const float*)d_in[8];
    const float* w2 = (const float*)d_in[9];
    const float* g2 = (const float*)d_in[10];
    const float* b2 = (const float*)d_in[11];
    const float* m2 = (const float*)d_in[12];
    const float* v2 = (const float*)d_in[13];
    float* out = (float*)d_out;

    float* vol = nullptr; float* x1 = nullptr;
    uint4* bf1 = nullptr; uint4* bf2 = nullptr;
    cudaGetSymbolAddress((void**)&vol, g_vol);
    cudaGetSymbolAddress((void**)&x1,  g_x1);
    cudaGetSymbolAddress((void**)&bf1, g_bf1);
    cudaGetSymbolAddress((void**)&bf2, g_bf2);

    // 1) cost volume
    dim3 gv(BB * HH_, 11);
    build_volume_kernel<<<gv, 256>>>(lg, rg, lc, rc);

    // 1b) weight prepack into mma fragments
    prepack_w<<<27, 256>>>(w1, w2);

    // 2) conv1 (64->32), split by batch so ncu's skip-5 capture lands on it
    dim3 gc(HH_, DD_, 1);
    conv_mma<64, 4, 144><<<gc, 128>>>(vol, bf1, g1, b1, m1, v1, x1, 0);
    conv_mma<64, 4, 144><<<gc, 128>>>(vol, bf1, g1, b1, m1, v1, x1, 1);
    conv_mma<64, 4, 144><<<gc, 128>>>(vol, bf1, g1, b1, m1, v1, x1, 2);
    conv_mma<64, 4, 144><<<gc, 128>>>(vol, bf1, g1, b1, m1, v1, x1, 3);

    // 3) conv2 (32->32)
    dim3 gc2(HH_, DD_, BB);
    conv_mma<32, 2, 80><<<gc2, 128>>>(x1, bf2, g2, b2, m2, v2, out, 0);
}